// round 11
// baseline (speedup 1.0000x reference)
#include <cuda_runtime.h>
#include <cuda_bf16.h>
#include <math_constants.h>
#include <stdint.h>

#define KCODES 512
#define DDIM   64
#define QELEMS 4194304
#define NBLKG  296
#define NTHR   256
#define NTILES 1024
#define THRG   2e-4f          // gap threshold; filter err <= ~1e-5

__device__ double   g_partial[NBLKG];
__device__ unsigned g_count = 0;
// Packed B-fragments: index (nb*32+lane)*2 + {0,1}; nb = code-block of 8
__device__ uint4 g_wph[64 * 32 * 2];
__device__ uint4 g_wpl[64 * 32 * 2];

// ---- smem float offsets ----
#define OFF_SX    0           // [64][68] f32 exact x
#define OFF_SXH   4352        // [64][72] bf16 hi
#define OFF_SXL   6656        // [64][72] bf16 lo
#define OFF_SB    8960        // [512] exact code norms
#define OFF_SA    9472        // [64] exact row norms
#define OFF_WD1   9536        // [8][64] per-warp min1
#define OFF_WK1   10048       // [8][64] per-warp argmin1
#define OFF_WD2   10560       // [8][64] per-warp min2
#define OFF_WIN   11072       // [64] int winners
#define OFF_FLIST 11136       // [64] int flagged rows
#define OFF_FCNT  11200       // int
#define OFF_SRED  11202       // [256] double (11202*4 % 8 == 0)
#define SMEM_BYTES ((OFF_SRED + 512) * 4)   // 46856 B

// ---------------------------------------------------------------------------
// K1: split w into bf16 hi/lo and pack into MMA B-fragment order.
// For nb, lane: n = nb*8 + (lane>>2); ks in 0..3: kc = ks*16 + (lane&3)*2;
// u32 pair0 = {w[n][kc], w[n][kc+1]}, pair1 = {w[n][kc+8], w[n][kc+9]}.
// uint4 #0 = {ks0p0, ks0p1, ks1p0, ks1p1}, #1 = {ks2.., ks3..}
// ---------------------------------------------------------------------------
__device__ __forceinline__ unsigned bf2u(float a, float b) {
    __nv_bfloat162 h;
    h.x = __float2bfloat16(a);
    h.y = __float2bfloat16(b);
    return *(unsigned*)&h;
}
__global__ void prep_w(const float* __restrict__ w) {
    int t = blockIdx.x * 256 + threadIdx.x;    // 0..2047
    int nb = t >> 5, lane = t & 31;
    int n  = nb * 8 + (lane >> 2);
    int c0 = (lane & 3) * 2;
    unsigned hh[8], ll[8];
    #pragma unroll
    for (int ks = 0; ks < 4; ks++) {
        int kc = ks * 16 + c0;
        #pragma unroll
        for (int p = 0; p < 2; p++) {
            float v0 = w[n * DDIM + kc + p * 8];
            float v1 = w[n * DDIM + kc + p * 8 + 1];
            __nv_bfloat16 h0 = __float2bfloat16(v0);
            __nv_bfloat16 h1 = __float2bfloat16(v1);
            float l0 = __fsub_rn(v0, __bfloat162float(h0));
            float l1 = __fsub_rn(v1, __bfloat162float(h1));
            __nv_bfloat162 hp; hp.x = h0; hp.y = h1;
            hh[ks * 2 + p] = *(unsigned*)&hp;
            ll[ks * 2 + p] = bf2u(l0, l1);
        }
    }
    int base = (nb * 32 + lane) * 2;
    g_wph[base]     = make_uint4(hh[0], hh[1], hh[2], hh[3]);
    g_wph[base + 1] = make_uint4(hh[4], hh[5], hh[6], hh[7]);
    g_wpl[base]     = make_uint4(ll[0], ll[1], ll[2], ll[3]);
    g_wpl[base + 1] = make_uint4(ll[4], ll[5], ll[6], ll[7]);
}

// ---------------------------------------------------------------------------
__device__ __forceinline__ void mma_bf16(float c[4], const unsigned a[4],
                                         unsigned b0, unsigned b1) {
    asm volatile(
        "mma.sync.aligned.m16n8k16.row.col.f32.bf16.bf16.f32 "
        "{%0,%1,%2,%3},{%4,%5,%6,%7},{%8,%9},{%0,%1,%2,%3};"
        : "+f"(c[0]), "+f"(c[1]), "+f"(c[2]), "+f"(c[3])
        : "r"(a[0]), "r"(a[1]), "r"(a[2]), "r"(a[3]), "r"(b0), "r"(b1));
}

__device__ __forceinline__ void upd2(float d, int k, float& d1, int& k1, float& d2) {
    if (d < d1) { d2 = d1; d1 = d; k1 = k; }
    else if (d < d2) d2 = d;
}
__device__ __forceinline__ void mrg(float& d1, int& k1, float& d2, int m) {
    float od1 = __shfl_xor_sync(0xffffffffu, d1, m);
    int   ok1 = __shfl_xor_sync(0xffffffffu, k1, m);
    float od2 = __shfl_xor_sync(0xffffffffu, d2, m);
    if (od1 < d1) { d2 = fminf(d1, od2); d1 = od1; k1 = ok1; }
    else          { d2 = fminf(d2, od1); }
}

// Zero 64 enc rows; enc base only 4B-aligned -> scalar fringes
__device__ __forceinline__ void zero_rows(float* __restrict__ enc,
                                          int row0, int tid) {
    float* p = enc + (size_t)row0 * KCODES;
    const int n = 64 * KCODES;
    uintptr_t a = (uintptr_t)p;
    int head = (int)((((a + 15) & ~(uintptr_t)15) - a) >> 2);
    if (tid < head) p[tid] = 0.0f;
    int n4 = (n - head) >> 2;
    int tail = (n - head) & 3;
    float4* v = (float4*)(p + head);
    float4 z = make_float4(0.f, 0.f, 0.f, 0.f);
    for (int i = tid; i < n4; i += NTHR) v[i] = z;
    if (tid >= 4 && tid - 4 < tail) p[head + 4 * n4 + (tid - 4)] = 0.0f;
}

// ---------------------------------------------------------------------------
__global__ void __launch_bounds__(NTHR, 1) vq_main(
    const float* __restrict__ x,
    const float* __restrict__ w,
    float* __restrict__ out,
    float* __restrict__ qout,
    float* __restrict__ enc)
{
    extern __shared__ float sm[];
    float* sx  = sm + OFF_SX;
    __nv_bfloat16* sxh = (__nv_bfloat16*)(sm + OFF_SXH);
    __nv_bfloat16* sxl = (__nv_bfloat16*)(sm + OFF_SXL);
    float* sb  = sm + OFF_SB;
    float* sa  = sm + OFF_SA;
    float* wd1 = sm + OFF_WD1;
    int*   wk1 = (int*)(sm + OFF_WK1);
    float* wd2 = sm + OFF_WD2;
    int*   win = (int*)(sm + OFF_WIN);
    int*   flist = (int*)(sm + OFF_FLIST);
    int*   fcnt  = (int*)(sm + OFF_FCNT);
    double* sred = (double*)(sm + OFF_SRED);

    const int tid  = threadIdx.x;
    const int bid  = blockIdx.x;
    const int wid  = tid >> 5;
    const int lane = tid & 31;

    // Exact code norms (reference chain) once per block
    for (int k = tid; k < KCODES; k += NTHR) {
        float acc = 0.0f;
        #pragma unroll
        for (int d = 0; d < DDIM; d++) {
            float v = w[k * DDIM + d];
            acc = __fadd_rn(acc, __fmul_rn(v, v));
        }
        sb[k] = acc;
    }

    double ls = 0.0;

    for (int it = 0; it < 4; it++) {
        const int t = bid + NBLKG * it;
        if (t >= NTILES) break;
        const int row0 = t * 64;
        __syncthreads();   // previous tile's smem fully consumed

        if (tid == 0) *fcnt = 0;
        zero_rows(enc, row0, tid);   // drains under compute

        // ---- Stage x tile: fp32 + bf16 hi/lo -----------------------------
        #pragma unroll
        for (int i = 0; i < 16; i++) {
            int idx = i * NTHR + tid;
            int r = idx & 63, d = idx >> 6;
            int n = row0 + r, b = n >> 10, hw = n & 1023;
            float v = x[(size_t)b * 65536 + hw + (size_t)d * 1024];
            sx[r * 68 + d] = v;
            __nv_bfloat16 h = __float2bfloat16(v);
            sxh[r * 72 + d] = h;
            sxl[r * 72 + d] = __float2bfloat16(__fsub_rn(v, __bfloat162float(h)));
        }
        __syncthreads();

        if (tid < 64) {
            const float* pr = sx + tid * 68;
            float acc = 0.0f;
            #pragma unroll
            for (int d = 0; d < DDIM; d++)
                acc = __fadd_rn(acc, __fmul_rn(pr[d], pr[d]));
            sa[tid] = acc;
        }
        __syncthreads();

        // ---- Load this warp's B-fragments into registers (once/tile) -----
        uint4 BH[8][2], BL[8][2];
        #pragma unroll
        for (int nt = 0; nt < 8; nt++) {
            int nb = wid * 8 + nt;
            int base = (nb * 32 + lane) * 2;
            BH[nt][0] = g_wph[base];     BH[nt][1] = g_wph[base + 1];
            BL[nt][0] = g_wpl[base];     BL[nt][1] = g_wpl[base + 1];
        }

        // ---- MMA + streaming (min1, argmin1, min2) per row ---------------
        #pragma unroll 1
        for (int mt = 0; mt < 4; mt++) {
            const int rr = mt * 16 + (lane >> 2);
            unsigned ah[4][4], al[4][4];
            {
                int c = (lane & 3) * 2;
                #pragma unroll
                for (int ks = 0; ks < 4; ks++) {
                    int kc = ks * 16 + c;
                    ah[ks][0] = *(const unsigned*)(sxh + rr * 72 + kc);
                    ah[ks][1] = *(const unsigned*)(sxh + (rr + 8) * 72 + kc);
                    ah[ks][2] = *(const unsigned*)(sxh + rr * 72 + kc + 8);
                    ah[ks][3] = *(const unsigned*)(sxh + (rr + 8) * 72 + kc + 8);
                    al[ks][0] = *(const unsigned*)(sxl + rr * 72 + kc);
                    al[ks][1] = *(const unsigned*)(sxl + (rr + 8) * 72 + kc);
                    al[ks][2] = *(const unsigned*)(sxl + rr * 72 + kc + 8);
                    al[ks][3] = *(const unsigned*)(sxl + (rr + 8) * 72 + kc + 8);
                }
            }
            float saA = sa[rr], saB = sa[rr + 8];
            float d1a = CUDART_INF_F, d2a = CUDART_INF_F;
            float d1b = CUDART_INF_F, d2b = CUDART_INF_F;
            int   k1a = 0, k1b = 0;

            #pragma unroll
            for (int nt = 0; nt < 8; nt++) {
                float acc[4] = {0.f, 0.f, 0.f, 0.f};
                #pragma unroll
                for (int ks = 0; ks < 4; ks++) {
                    unsigned b0h = (ks == 0) ? BH[nt][0].x : (ks == 1) ? BH[nt][0].z
                                 : (ks == 2) ? BH[nt][1].x : BH[nt][1].z;
                    unsigned b1h = (ks == 0) ? BH[nt][0].y : (ks == 1) ? BH[nt][0].w
                                 : (ks == 2) ? BH[nt][1].y : BH[nt][1].w;
                    unsigned b0l = (ks == 0) ? BL[nt][0].x : (ks == 1) ? BL[nt][0].z
                                 : (ks == 2) ? BL[nt][1].x : BL[nt][1].z;
                    unsigned b1l = (ks == 0) ? BL[nt][0].y : (ks == 1) ? BL[nt][0].w
                                 : (ks == 2) ? BL[nt][1].y : BL[nt][1].w;
                    mma_bf16(acc, al[ks], b0h, b1h);
                    mma_bf16(acc, ah[ks], b0l, b1l);
                    mma_bf16(acc, ah[ks], b0h, b1h);
                }
                const int nn = wid * 64 + nt * 8 + (lane & 3) * 2;
                float sb0 = sb[nn], sb1 = sb[nn + 1];
                upd2(saA + sb0 - 2.0f * acc[0], nn,     d1a, k1a, d2a);
                upd2(saA + sb1 - 2.0f * acc[1], nn + 1, d1a, k1a, d2a);
                upd2(saB + sb0 - 2.0f * acc[2], nn,     d1b, k1b, d2b);
                upd2(saB + sb1 - 2.0f * acc[3], nn + 1, d1b, k1b, d2b);
            }
            // merge across the 4 lanes sharing each row
            mrg(d1a, k1a, d2a, 1); mrg(d1a, k1a, d2a, 2);
            mrg(d1b, k1b, d2b, 1); mrg(d1b, k1b, d2b, 2);
            if ((lane & 3) == 0) {
                wd1[wid * 64 + rr] = d1a; wk1[wid * 64 + rr] = k1a;
                wd2[wid * 64 + rr] = d2a;
                wd1[wid * 64 + rr + 8] = d1b; wk1[wid * 64 + rr + 8] = k1b;
                wd2[wid * 64 + rr + 8] = d2b;
            }
        }
        __syncthreads();

        // ---- Per-row merge over 8 warps + gap decision -------------------
        if (tid < 64) {
            float d1 = CUDART_INF_F, d2 = CUDART_INF_F; int k1 = 0;
            #pragma unroll
            for (int ww = 0; ww < 8; ww++) {
                float od1 = wd1[ww * 64 + tid];
                float od2 = wd2[ww * 64 + tid];
                int   ok1 = wk1[ww * 64 + tid];
                if (od1 < d1) { d2 = fminf(d1, od2); d1 = od1; k1 = ok1; }
                else          { d2 = fminf(d2, od1); }
            }
            if (d2 - d1 > THRG) {
                win[tid] = k1;             // provably the exact argmin
            } else {
                int idx = atomicAdd(fcnt, 1);
                flist[idx] = tid;          // rare: exact full rescan
            }
        }
        __syncthreads();

        // ---- Warp-parallel exact rescan of flagged rows ------------------
        {
            int nf = *fcnt;
            for (int i = wid; i < nf; i += 8) {
                int r = flist[i];
                float xr[DDIM];
                #pragma unroll
                for (int d = 0; d < DDIM; d++) xr[d] = sx[r * 68 + d];  // bcast
                float a = sa[r];
                float best = CUDART_INF_F; int bi = 0x7fffffff;
                #pragma unroll 1
                for (int j = 0; j < 16; j++) {
                    int k = lane + 32 * j;
                    const float* wk = w + (size_t)k * DDIM;
                    float m = 0.0f;
                    #pragma unroll
                    for (int d = 0; d < DDIM; d++)
                        m = __fmaf_rn(xr[d], wk[d], m);   // reference chain
                    float dd = __fsub_rn(__fadd_rn(a, sb[k]), __fmul_rn(2.0f, m));
                    if (dd < best || (dd == best && k < bi)) { best = dd; bi = k; }
                }
                #pragma unroll
                for (int m2 = 16; m2 > 0; m2 >>= 1) {
                    float od = __shfl_xor_sync(0xffffffffu, best, m2);
                    int   ok = __shfl_xor_sync(0xffffffffu, bi,   m2);
                    if (od < best || (od == best && ok < bi)) { best = od; bi = ok; }
                }
                if (lane == 0) win[r] = bi;
            }
        }
        __syncthreads();

        // ---- Epilogue: q_out (straight-through), one-hot, loss -----------
        #pragma unroll
        for (int i = 0; i < 16; i++) {
            int idx = i * NTHR + tid;
            int r = idx & 63, d = idx >> 6;
            int n = row0 + r, b = n >> 10, hw = n & 1023;
            int bi = win[r];
            float xv   = sx[r * 68 + d];
            float diff = __fsub_rn(w[(size_t)bi * DDIM + d], xv);
            qout[(size_t)b * 65536 + hw + (size_t)d * 1024] = __fadd_rn(xv, diff);
            ls += (double)__fmul_rn(diff, diff);
        }
        if (tid < 64)
            enc[(size_t)(row0 + tid) * KCODES + win[tid]] = 1.0f;
    }

    // ---- Deterministic loss reduction -------------------------------------
    __syncthreads();
    sred[tid] = ls;
    __syncthreads();
    for (int s = NTHR / 2; s > 0; s >>= 1) {
        if (tid < s) sred[tid] += sred[tid + s];
        __syncthreads();
    }
    __shared__ int isLast;
    if (tid == 0) {
        g_partial[bid] = sred[0];
        __threadfence();
        unsigned old = atomicAdd(&g_count, 1u);
        isLast = (old == NBLKG - 1u) ? 1 : 0;
    }
    __syncthreads();
    if (isLast) {
        double v = g_partial[tid];
        if (tid + 256 < NBLKG) v += g_partial[tid + 256];
        sred[tid] = v;
        __syncthreads();
        for (int s = NTHR / 2; s > 0; s >>= 1) {
            if (tid < s) sred[tid] += sred[tid + s];
            __syncthreads();
        }
        if (tid == 0) {
            float m = (float)(sred[0] / (double)QELEMS);
            out[0] = __fadd_rn(m, __fmul_rn(0.25f, m));   // z_q + 0.25*z_e
            g_count = 0;                                  // reset for replay
        }
    }
}

// ---------------------------------------------------------------------------
extern "C" void kernel_launch(void* const* d_in, const int* in_sizes, int n_in,
                              void* d_out, int out_size) {
    const float* x = (const float*)d_in[0];   // [64,64,32,32] fp32
    const float* w = (const float*)d_in[1];   // [512,64] fp32
    float* out  = (float*)d_out;
    float* qout = out + 1;                    // [4194304] (4B-aligned only)
    float* enc  = out + 1 + QELEMS;           // [65536*512] (4B-aligned only)

    cudaFuncSetAttribute(vq_main, cudaFuncAttributeMaxDynamicSharedMemorySize,
                         SMEM_BYTES);

    prep_w<<<8, 256>>>(w);
    vq_main<<<NBLKG, NTHR, SMEM_BYTES>>>(x, w, out, qout, enc);
}